// round 8
// baseline (speedup 1.0000x reference)
#include <cuda_runtime.h>
#include <cstdint>

// B=32, N=64, D=512
// score[b,i,j] = (dot(s_e[b,i,j,:], W) + bias) * adj[b,i,j], adj[b,0,1]=adj[b,1,0]=0
// Only i in {0,1} consumed. Outputs (float32, flattened tuple order):
//   final_id (32,2)=64 | s_e_score (32,2,64)=4096 | flag (32)=32

#define NB 32
#define NN 64
#define ND 512
#define GRID 128
#define TPB  512   // 16 warps, 2 dot products per warp

__device__ int g_done_counter = 0;   // reset by last block each launch

// 32-byte load with L2 evict_last (sm_103a requires v8.b32 / v4.b64 shape).
__device__ __forceinline__ void ldg_el32(const float* p, float* v) {
    uint32_t r0, r1, r2, r3, r4, r5, r6, r7;
    asm volatile(
        "ld.global.nc.L2::evict_last.v8.b32 {%0,%1,%2,%3,%4,%5,%6,%7}, [%8];"
        : "=r"(r0), "=r"(r1), "=r"(r2), "=r"(r3),
          "=r"(r4), "=r"(r5), "=r"(r6), "=r"(r7)
        : "l"(p));
    v[0] = __uint_as_float(r0); v[1] = __uint_as_float(r1);
    v[2] = __uint_as_float(r2); v[3] = __uint_as_float(r3);
    v[4] = __uint_as_float(r4); v[5] = __uint_as_float(r5);
    v[6] = __uint_as_float(r6); v[7] = __uint_as_float(r7);
}

__global__ void
fused_kernel(const float* __restrict__ s_e,
             const float* __restrict__ adj,
             const float* __restrict__ W,
             const float* __restrict__ bias,
             float* __restrict__ out_id,
             float* __restrict__ out_score,
             float* __restrict__ out_flag) {
    int warp = threadIdx.x >> 5;
    int lane = threadIdx.x & 31;

    // This warp's two flattened dot-product ids: p0 = row*64 + j (row = b*2+i)
    int p0 = (blockIdx.x * 16 + warp) * 2;       // 0..4094, even
    int b  = p0 >> 7;
    int i0 = (p0 >> 6) & 1;
    int j0 = p0 & 63;                            // j1 = j0+1, same row

    // Per-lane element offsets within a 512-float row: 8 floats at lane*8,
    // and 8 floats at 256 + lane*8 (two 32B chunks per lane).
    const float* row0 = s_e + ((size_t)((b * NN + i0) * NN + j0)) * ND;
    const float* row1 = row0 + ND;               // j0+1
    int o0 = lane * 8;
    int o1 = 256 + lane * 8;

    // adj for both j's: lanes 0/1 fetch, broadcast later.
    float adj_mine = 0.f;
    if (lane < 2)
        adj_mine = adj[(b * NN + i0) * NN + j0 + lane];
    float bias0 = __ldg(bias);

    // ---------- FRONT-BATCH ALL LOADS (single latency exposure) ----------
    float a0[8], a1[8], c0[8], c1[8], wA[8], wB[8];
    ldg_el32(row0 + o0, a0);
    ldg_el32(row0 + o1, a1);
    ldg_el32(row1 + o0, c0);
    ldg_el32(row1 + o1, c1);
    ldg_el32(W + o0, wA);
    ldg_el32(W + o1, wB);

    // ---------- compute both dots ----------
    float s0 = 0.f, s1 = 0.f;
#pragma unroll
    for (int k = 0; k < 8; ++k) {
        s0 += a0[k] * wA[k] + a1[k] * wB[k];
        s1 += c0[k] * wA[k] + c1[k] * wB[k];
    }

#pragma unroll
    for (int off = 16; off; off >>= 1) {
        s0 += __shfl_xor_sync(0xffffffffu, s0, off);
        s1 += __shfl_xor_sync(0xffffffffu, s1, off);
    }
    float adj0 = __shfl_sync(0xffffffffu, adj_mine, 0);
    float adj1 = __shfl_sync(0xffffffffu, adj_mine, 1);

    if (lane == 0) {
        if (i0 == 0 && j0 == 0) adj1 = 0.f;          // (i=0, j=1)
        if (i0 == 1 && j0 == 0) adj0 = 0.f;          // (i=1, j=0)
        float2 sc = make_float2((s0 + bias0) * adj0, (s1 + bias0) * adj1);
        *(float2*)(out_score + p0) = sc;             // 8B aligned (p0 even)
    }

    // ---------- handshake: last block runs the epilogue ----------
    __syncthreads();
    __shared__ bool is_last;
    if (threadIdx.x == 0) {
        __threadfence();
        int prev = atomicAdd(&g_done_counter, 1);
        is_last = (prev == GRID - 1);
    }
    __syncthreads();
    if (!is_last) return;
    __threadfence();   // acquire

    // ---------- epilogue: 64 row argmaxes + flags (L2-hot) ----------
    __shared__ int s_ids[64];
#pragma unroll
    for (int r = 0; r < 4; ++r) {
        int row = warp * 4 + r;                      // 0..63 == b*2 + i
        const float* rp = out_score + row * NN;
        float v0 = rp[lane];
        float v1 = rp[lane + 32];
        float v; int idx;
        if (v1 > v0) { v = v1; idx = lane + 32; }
        else         { v = v0; idx = lane; }
#pragma unroll
        for (int off = 16; off; off >>= 1) {
            float ov = __shfl_xor_sync(0xffffffffu, v, off);
            int   oi = __shfl_xor_sync(0xffffffffu, idx, off);
            if (ov > v || (ov == v && oi < idx)) { v = ov; idx = oi; }
        }
        if (lane == 0) {
            s_ids[row] = idx;
            out_id[row] = (float)idx;
        }
    }
    __syncthreads();

    if (threadIdx.x < NB) {
        int sub = s_ids[threadIdx.x * 2];
        int obj = s_ids[threadIdx.x * 2 + 1];
        float f = 0.f;
        if (sub > 0 && obj > 0)      f = 3.f;
        else if (sub > 0)            f = 1.f;
        else if (obj > 0)            f = 2.f;
        out_flag[threadIdx.x] = f;
    }

    if (threadIdx.x == 0) g_done_counter = 0;        // deterministic replays
}

extern "C" void kernel_launch(void* const* d_in, const int* in_sizes, int n_in,
                              void* d_out, int out_size) {
    const float* s_e  = (const float*)d_in[0];
    const float* adj  = (const float*)d_in[1];
    const float* W    = (const float*)d_in[2];
    const float* bias = (const float*)d_in[3];

    float* out       = (float*)d_out;
    float* out_id    = out;             // 64
    float* out_score = out + 64;        // 4096
    float* out_flag  = out + 64 + 4096; // 32

    fused_kernel<<<GRID, TPB>>>(s_e, adj, W, bias, out_id, out_score, out_flag);
}